// round 1
// baseline (speedup 1.0000x reference)
#include <cuda_runtime.h>
#include <cstdint>

#define NB   32
#define NS   1024
#define ROWS (NB * NS)       // 32768
#define KNN  32
#define NIN  64              // 2*K
#define MID  32

// packed f32x2 FMA (sm_100+)
__device__ __forceinline__ unsigned long long fma2(unsigned long long a,
                                                   unsigned long long b,
                                                   unsigned long long c) {
    unsigned long long d;
    asm("fma.rn.f32x2 %0, %1, %2, %3;" : "=l"(d) : "l"(a), "l"(b), "l"(c));
    return d;
}

__device__ __forceinline__ unsigned long long pack2(float lo, float hi) {
    unsigned long long d;
    asm("mov.b64 %0, {%1, %2};" : "=l"(d) : "f"(lo), "f"(hi));
    return d;
}

__device__ __forceinline__ void unpack2(unsigned long long v, float& lo, float& hi) {
    asm("mov.b64 {%0, %1}, %2;" : "=f"(lo), "=f"(hi) : "l"(v));
}

// tanh(x) = 1 - 2/(exp(2x)+1), via ex2.approx + rcp.approx (~1e-6 rel err)
__device__ __forceinline__ float fast_tanh(float x) {
    float e, r;
    asm("ex2.approx.f32 %0, %1;" : "=f"(e) : "f"(x * 2.8853900817779268f)); // 2*log2(e)
    asm("rcp.approx.f32 %0, %1;" : "=f"(r) : "f"(e + 1.0f));
    return fmaf(-2.0f, r, 1.0f);
}

__global__ __launch_bounds__(256)
void metak_kernel(const int*   __restrict__ vals,
                  const float* __restrict__ dist,
                  const float* __restrict__ fc2_w1,   // [64,32]
                  const float* __restrict__ fc2_b1,   // [32]
                  const float* __restrict__ fc2_w2,   // [32,2]
                  const float* __restrict__ fc2_b2,   // [2]
                  const float* __restrict__ fc1_w1,   // [2,4]
                  const float* __restrict__ fc1_b1,   // [4]
                  const float* __restrict__ fc1_w2,   // [4,1]
                  const float* __restrict__ fc1_b2,   // [1]
                  float*       __restrict__ out)
{
    __shared__ __align__(16) float sw1[NIN * MID];   // 2048 floats, 8KB
    __shared__ float sb1[MID];
    __shared__ float sw2[MID * 2];
    __shared__ float sb2[2];
    __shared__ float sf1w1[8];
    __shared__ float sf1b1[4];
    __shared__ float sf1w2[4];
    __shared__ float sf1b2;

    const int tid = threadIdx.x;
    for (int i = tid; i < NIN * MID; i += blockDim.x) sw1[i] = fc2_w1[i];
    if (tid < MID)     sb1[tid]       = fc2_b1[tid];
    if (tid < MID * 2) sw2[tid]       = fc2_w2[tid];
    if (tid < 2)       sb2[tid]       = fc2_b2[tid];
    if (tid < 8)       sf1w1[tid]     = fc1_w1[tid];
    if (tid < 4)       sf1b1[tid]     = fc1_b1[tid];
    if (tid < 4)       sf1w2[tid]     = fc1_w2[tid];
    if (tid == 0)      sf1b2          = fc1_b2[0];
    __syncthreads();

    const int row = blockIdx.x * blockDim.x + tid;   // grid sized exactly to ROWS
    if (row >= ROWS) return;

    // ---- load this row's 32 labels + 32 distances with 128-bit loads ----
    const int4*   vp = reinterpret_cast<const int4*>(vals + (size_t)row * KNN);
    const float4* dp = reinterpret_cast<const float4*>(dist + (size_t)row * KNN);

    int vv[KNN];
    float x[NIN];
#pragma unroll
    for (int i = 0; i < 8; i++) {
        int4   v4 = vp[i];
        float4 d4 = dp[i];
        vv[4*i+0] = v4.x; vv[4*i+1] = v4.y; vv[4*i+2] = v4.z; vv[4*i+3] = v4.w;
        x[4*i+0] = d4.x;  x[4*i+1] = d4.y;  x[4*i+2] = d4.z;  x[4*i+3] = d4.w;
    }

    // ---- prefix count of distinct NONZERO labels (labels in [0,100)) ----
    // bit 0 of m0 pre-set so label 0 is never counted as new.
    unsigned long long m0 = 1ull, m1 = 0ull;
    int cnt = 0;
#pragma unroll
    for (int i = 0; i < KNN; i++) {
        int v = vv[i];
        unsigned long long bit = 1ull << (v & 63);
        bool hi = (v & 64) != 0;
        unsigned long long cur = hi ? m1 : m0;
        cnt += (int)((cur & bit) == 0ull);
        cur |= bit;
        if (hi) m1 = cur; else m0 = cur;
        x[KNN + i] = (float)cnt;
    }

    // ---- fc2 layer 1: x[64] @ w1[64,32] + b1, packed f32x2 ----
    unsigned long long acc[MID / 2];
#pragma unroll
    for (int j = 0; j < MID / 2; j++) acc[j] = pack2(sb1[2*j], sb1[2*j+1]);

#pragma unroll
    for (int k = 0; k < NIN; k++) {
        unsigned long long xp = pack2(x[k], x[k]);
        const ulonglong2* wrow = reinterpret_cast<const ulonglong2*>(sw1 + k * MID);
#pragma unroll
        for (int q = 0; q < 8; q++) {
            ulonglong2 w = wrow[q];
            acc[2*q]   = fma2(xp, w.x, acc[2*q]);
            acc[2*q+1] = fma2(xp, w.y, acc[2*q+1]);
        }
    }

    float h[MID];
#pragma unroll
    for (int j = 0; j < MID / 2; j++) {
        float a, b;
        unpack2(acc[j], a, b);
        h[2*j]   = fast_tanh(a);
        h[2*j+1] = fast_tanh(b);
    }

    // ---- fc2 layer 2: h[32] @ w2[32,2] + b2 ----
    float o0 = sb2[0], o1 = sb2[1];
#pragma unroll
    for (int j = 0; j < MID; j++) {
        float hj = h[j];
        o0 = fmaf(hj, sw2[2*j],   o0);
        o1 = fmaf(hj, sw2[2*j+1], o1);
    }

    // ---- fc1 head: [o0,o1] -> 4 (tanh) -> 1 ----
    float r = sf1b2;
#pragma unroll
    for (int c = 0; c < 4; c++) {
        float t = fast_tanh(fmaf(o1, sf1w1[4 + c], fmaf(o0, sf1w1[c], sf1b1[c])));
        r = fmaf(t, sf1w2[c], r);
    }

    float* op = out + (size_t)row * 3;
    op[0] = o0;
    op[1] = o1;
    op[2] = r;
}

extern "C" void kernel_launch(void* const* d_in, const int* in_sizes, int n_in,
                              void* d_out, int out_size)
{
    const int*   vals   = (const int*)  d_in[0];
    const float* dist   = (const float*)d_in[1];
    const float* fc2_w1 = (const float*)d_in[2];
    const float* fc2_b1 = (const float*)d_in[3];
    const float* fc2_w2 = (const float*)d_in[4];
    const float* fc2_b2 = (const float*)d_in[5];
    const float* fc1_w1 = (const float*)d_in[6];
    const float* fc1_b1 = (const float*)d_in[7];
    const float* fc1_w2 = (const float*)d_in[8];
    const float* fc1_b2 = (const float*)d_in[9];
    float* out = (float*)d_out;

    const int threads = 256;
    const int blocks  = ROWS / threads;  // 128
    metak_kernel<<<blocks, threads>>>(vals, dist,
                                      fc2_w1, fc2_b1, fc2_w2, fc2_b2,
                                      fc1_w1, fc1_b1, fc1_w2, fc1_b2,
                                      out);
}